// round 2
// baseline (speedup 1.0000x reference)
#include <cuda_runtime.h>

#define Bz 128
#define Sz 1024
#define Dz 64
#define Hz 128
#define Oz 512
#define Mz (Bz*Sz)   /* 131072 */

// ---- static device scratch (no allocations allowed) ----
__device__ float g_pt [(size_t)Mz*Hz];   // encoder output [M][H]
__device__ float g_phT[(size_t)Hz*Mz];   // ph transposed [H][M]
__device__ float g_wbT[(size_t)Hz*Mz];   // wb transposed [H][M]
__device__ float g_Wrp[Hz*7*Oz];         // Wr permuted: [h][jf][o]
__device__ int   g_rep[Sz];

// ---- helpers ----
__device__ __forceinline__ float wrap_pi(float x){
    // Cody-Waite 2-term reduction to [-pi, pi]
    float k = rintf(x * 0.15915494309189535f);
    float r = fmaf(k, -6.28125f, x);
    r = fmaf(k, -1.9353071795864769e-3f, r);
    return r;
}
__device__ __forceinline__ float fsin(float x){ return __sinf(wrap_pi(x)); }
__device__ __forceinline__ void fsincos(float x, float* s, float* c){
    float r = wrap_pi(x);
    __sincosf(r, s, c);
}
__device__ __forceinline__ float2 ffma2(float2 a, float2 b, float2 c){
    unsigned long long ua = reinterpret_cast<unsigned long long&>(a);
    unsigned long long ub = reinterpret_cast<unsigned long long&>(b);
    unsigned long long uc = reinterpret_cast<unsigned long long&>(c);
    unsigned long long ud;
    asm("fma.rn.f32x2 %0, %1, %2, %3;" : "=l"(ud) : "l"(ua), "l"(ub), "l"(uc));
    return reinterpret_cast<float2&>(ud);
}

// ---- 1) encoder: pt[m][h] = x[m][:] . We[h][:] + be[h] ----
__global__ __launch_bounds__(256) void encoder_kernel(const float* __restrict__ x,
                                                      const float* __restrict__ We,
                                                      const float* __restrict__ be){
    __shared__ __align__(16) float WeT[Dz*Hz];  // [k][h]
    __shared__ float xs[32*Dz];
    int t = threadIdx.x;
    int m0 = blockIdx.x * 32;
    for (int i = t; i < Dz*Hz; i += 256){ int h = i >> 6, k = i & 63; WeT[k*Hz + h] = We[i]; }
    for (int i = t; i < 32*Dz; i += 256) xs[i] = x[(size_t)m0*Dz + i];
    __syncthreads();
    int r = t >> 3, hg = t & 7;   // row 0..31, h-group 0..7 (16 h each)
    float acc[16];
    #pragma unroll
    for (int j = 0; j < 16; j++) acc[j] = 0.f;
    #pragma unroll 4
    for (int k = 0; k < Dz; k++){
        float xv = xs[r*Dz + k];
        const float4* wp = (const float4*)&WeT[k*Hz + hg*16];
        float4 w0 = wp[0], w1 = wp[1], w2 = wp[2], w3 = wp[3];
        acc[0]  = fmaf(xv, w0.x, acc[0]);  acc[1]  = fmaf(xv, w0.y, acc[1]);
        acc[2]  = fmaf(xv, w0.z, acc[2]);  acc[3]  = fmaf(xv, w0.w, acc[3]);
        acc[4]  = fmaf(xv, w1.x, acc[4]);  acc[5]  = fmaf(xv, w1.y, acc[5]);
        acc[6]  = fmaf(xv, w1.z, acc[6]);  acc[7]  = fmaf(xv, w1.w, acc[7]);
        acc[8]  = fmaf(xv, w2.x, acc[8]);  acc[9]  = fmaf(xv, w2.y, acc[9]);
        acc[10] = fmaf(xv, w2.z, acc[10]); acc[11] = fmaf(xv, w2.w, acc[11]);
        acc[12] = fmaf(xv, w3.x, acc[12]); acc[13] = fmaf(xv, w3.y, acc[13]);
        acc[14] = fmaf(xv, w3.z, acc[14]); acc[15] = fmaf(xv, w3.w, acc[15]);
    }
    int m = m0 + r;
    #pragma unroll
    for (int j = 0; j < 16; j++){
        int h = hg*16 + j;
        g_pt[(size_t)m*Hz + h] = acc[j] + be[h];
    }
}

// ---- 2) repeat flags: rep[s] = all(x[:,s,:] == x[:,s-1,:]) ----
__global__ void rep_kernel(const float* __restrict__ x){
    int s = blockIdx.x;
    int ok;
    if (s > 0){
        ok = 1;
        for (int i = threadIdx.x; i < Bz*Dz; i += 256){
            int b = i >> 6, d = i & 63;
            size_t idx = ((size_t)b*Sz + s)*Dz + d;
            if (x[idx] != x[idx - Dz]) { ok = 0; break; }
        }
    } else {
        ok = 0;
    }
    ok = __syncthreads_and(ok);
    if (threadIdx.x == 0) g_rep[s] = ok;
}

// ---- 3) recurrence: one thread per (b,h) ----
__global__ __launch_bounds__(128) void recur_kernel(const float* __restrict__ omega,
                                                    float* __restrict__ out_ph,
                                                    float* __restrict__ out_wb){
    int b = blockIdx.x, h = threadIdx.x;
    float om = omega[h];
    float ph = 0.f, wb = 0.f;
    const float* ptp = g_pt + (size_t)b*Sz*Hz + h;
    float* php = out_ph + (size_t)b*Sz*Hz + h;
    float* wbp = out_wb + (size_t)b*Sz*Hz + h;
    #pragma unroll 4
    for (int s = 0; s < Sz; s++){
        float pt = ptp[(size_t)s*Hz];
        wb += 0.015625f;                                   // WOBBLE_STEP
        // ph_new = ph + omega - sin(theta - ph) + 0.25*sin(wb);  theta==pt mod 2pi
        float phn = ph + om - fsin(pt - ph) + 0.25f*fsin(wb);
        if (g_rep[s]) wb += 0.25f*fsin(pt - wb);           // wobble relax on repeats
        ph = phn;
        php[(size_t)s*Hz] = ph;
        wbp[(size_t)s*Hz] = wb;
    }
}

// ---- 4) permute Wr[o][jf*128+h] -> g_Wrp[(h*7+jf)*O + o] ----
__global__ void wrperm_kernel(const float* __restrict__ Wr){
    int i = blockIdx.x*256 + threadIdx.x;
    if (i < Oz*7*Hz){
        int o = i / (7*Hz), c = i % (7*Hz);
        int jf = c / Hz, h = c % Hz;
        g_Wrp[(h*7 + jf)*Oz + o] = Wr[i];
    }
}

// ---- 5) transpose ph/wb hist [M][H] -> [H][M] ----
__global__ void transpose_kernel(const float* __restrict__ out_ph,
                                 const float* __restrict__ out_wb){
    __shared__ float tile[32][33];
    const float* src = blockIdx.z ? out_wb : out_ph;
    float*       dst = blockIdx.z ? g_wbT  : g_phT;
    int m0 = blockIdx.x*32, h0 = blockIdx.y*32;
    int tx = threadIdx.x, ty = threadIdx.y;
    #pragma unroll
    for (int r = 0; r < 4; r++)
        tile[ty + r*8][tx] = src[(size_t)(m0 + ty + r*8)*Hz + h0 + tx];
    __syncthreads();
    #pragma unroll
    for (int r = 0; r < 4; r++)
        dst[(size_t)(h0 + ty + r*8)*Mz + m0 + tx] = tile[tx][ty + r*8];
}

// ---- 6) readout GEMM: logits[m][o] = feats[m][:] . Wr[o][:] + br[o] ----
// K reordered h-major: for each h, 7 feature values generated on the fly.
// Tile: 128m x 128n per block, 256 threads, 8x8 micro-tile via f32x2 FMA.
__global__ __launch_bounds__(256) void readout_kernel(const float* __restrict__ br,
                                                      float* __restrict__ out){
    __shared__ float As[128][12];                 // feats column tile [m][jf], padded
    __shared__ __align__(16) float Bs[7][128];    // weight slice [jf][n]
    int t = threadIdx.x;
    int m0 = blockIdx.x*128, n0 = blockIdx.y*128;
    int tm = t >> 4, tn = t & 15;                 // tm 0..15, tn 0..15
    float2 acc[8][4];
    #pragma unroll
    for (int ii = 0; ii < 8; ii++)
        #pragma unroll
        for (int jc = 0; jc < 4; jc++) acc[ii][jc] = make_float2(0.f, 0.f);

    for (int h = 0; h < Hz; h++){
        if (t < 128){
            int m = m0 + t;
            float ph = g_phT[(size_t)h*Mz + m];
            float wb = g_wbT[(size_t)h*Mz + m];
            float s2, c2; fsincos(0.5f*ph, &s2, &c2);      // half angle
            float c1 = fmaf(2.f*c2, c2, -1.f);             // cos(ph)
            float s1 = 2.f*s2*c2;                          // sin(ph)
            float s3, c3; fsincos(wb, &s3, &c3);
            As[t][0] = c1; As[t][1] = s1; As[t][2] = c2; As[t][3] = s2;
            As[t][4] = c3; As[t][5] = s3; As[t][6] = ph;
        } else {
            int i = t - 128;                               // 0..127 -> 224 float4 loads
            {
                int jf = i >> 5, pos = (i & 31)*4;
                *(float4*)&Bs[jf][pos] = *(const float4*)&g_Wrp[(size_t)(h*7 + jf)*Oz + n0 + pos];
            }
            int i2 = i + 128;
            if (i2 < 224){
                int jf = i2 >> 5, pos = (i2 & 31)*4;
                *(float4*)&Bs[jf][pos] = *(const float4*)&g_Wrp[(size_t)(h*7 + jf)*Oz + n0 + pos];
            }
        }
        __syncthreads();
        #pragma unroll
        for (int jf = 0; jf < 7; jf++){
            float a[8];
            #pragma unroll
            for (int ii = 0; ii < 8; ii++) a[ii] = As[tm + ii*16][jf];
            float2 b2[4];
            #pragma unroll
            for (int jc = 0; jc < 4; jc++)
                b2[jc] = make_float2(Bs[jf][tn + jc*32], Bs[jf][tn + jc*32 + 16]);
            #pragma unroll
            for (int ii = 0; ii < 8; ii++){
                float2 a2 = make_float2(a[ii], a[ii]);
                #pragma unroll
                for (int jc = 0; jc < 4; jc++)
                    acc[ii][jc] = ffma2(a2, b2[jc], acc[ii][jc]);
            }
        }
        __syncthreads();
    }
    #pragma unroll
    for (int ii = 0; ii < 8; ii++){
        int m = m0 + tm + ii*16;
        #pragma unroll
        for (int jc = 0; jc < 4; jc++){
            int n = n0 + tn + jc*32;
            out[(size_t)m*Oz + n]      = acc[ii][jc].x + br[n];
            out[(size_t)m*Oz + n + 16] = acc[ii][jc].y + br[n + 16];
        }
    }
}

extern "C" void kernel_launch(void* const* d_in, const int* in_sizes, int n_in,
                              void* d_out, int out_size){
    const float* x     = (const float*)d_in[0];
    const float* We    = (const float*)d_in[1];
    const float* be    = (const float*)d_in[2];
    const float* omega = (const float*)d_in[3];
    const float* Wr    = (const float*)d_in[4];
    const float* br    = (const float*)d_in[5];
    float* out        = (float*)d_out;
    float* out_logits = out;                                  // [B,S,O]
    float* out_ph     = out + (size_t)Mz*Oz;                  // [B,S,H]
    float* out_wb     = out_ph + (size_t)Mz*Hz;               // [B,S,H]

    encoder_kernel<<<Mz/32, 256>>>(x, We, be);
    rep_kernel<<<Sz, 256>>>(x);
    wrperm_kernel<<<(Oz*7*Hz + 255)/256, 256>>>(Wr);
    recur_kernel<<<Bz, 128>>>(omega, out_ph, out_wb);
    transpose_kernel<<<dim3(Mz/32, Hz/32, 2), dim3(32, 8)>>>(out_ph, out_wb);
    readout_kernel<<<dim3(Mz/128, Oz/128), 256>>>(br, out_logits);
}

// round 7
// speedup vs baseline: 2.9363x; 2.9363x over previous
#include <cuda_runtime.h>
#include <cuda_fp16.h>
#include <cstdint>

#define Bz 128
#define Sz 1024
#define Dz 64
#define Hz 128
#define Oz 512
#define Mz (Bz*Sz)   /* 131072 */
#define Kz 1024      /* 8 fp16 feature cols per h * 128 h */

// ---- static device scratch ----
__device__ float g_pt [(size_t)Mz*Hz];                 // encoder output [M][H]
__device__ __align__(16) __half g_Bp[(size_t)Oz*Kz];   // permuted fp16 weights [n][k], k=h*8+jf
__device__ int   g_rep[Sz];

// ============================ helpers ============================
__device__ __forceinline__ uint32_t h2_to_u32(__half2 v){
    return *reinterpret_cast<uint32_t*>(&v);
}
__device__ __forceinline__ uint32_t smem_u32(const void* p){
    uint32_t a;
    asm("{ .reg .u64 t; cvta.to.shared.u64 t, %1; cvt.u32.u64 %0, t; }" : "=r"(a) : "l"(p));
    return a;
}
__device__ __forceinline__ uint32_t swz(uint32_t b){ return b ^ ((b >> 3) & 0x70); }

__device__ __forceinline__ void ldsm_x4(uint32_t* r, uint32_t addr){
    asm volatile("ldmatrix.sync.aligned.m8n8.x4.shared.b16 {%0,%1,%2,%3}, [%4];"
        : "=r"(r[0]), "=r"(r[1]), "=r"(r[2]), "=r"(r[3]) : "r"(addr));
}
__device__ __forceinline__ void mma16816(float* d, const uint32_t* a, const uint32_t* b){
    asm volatile("mma.sync.aligned.m16n8k16.row.col.f32.f16.f16.f32 "
        "{%0,%1,%2,%3}, {%4,%5,%6,%7}, {%8,%9}, {%0,%1,%2,%3};"
        : "+f"(d[0]), "+f"(d[1]), "+f"(d[2]), "+f"(d[3])
        : "r"(a[0]), "r"(a[1]), "r"(a[2]), "r"(a[3]), "r"(b[0]), "r"(b[1]));
}

// ---- fast sin/sincos with magic-number range reduction ----
__device__ __forceinline__ float wrap_pi(float x){
    float k = fmaf(x, 0.15915494309189535f, 12582912.0f);
    k -= 12582912.0f;
    float r = fmaf(k, -6.28125f, x);
    r = fmaf(k, -1.9353071795864769e-3f, r);
    return r;
}
__device__ __forceinline__ float fsin(float x){ return __sinf(wrap_pi(x)); }
__device__ __forceinline__ void fsincos(float x, float* s, float* c){ __sincosf(wrap_pi(x), s, c); }

// ============================ 1) encoder ============================
__global__ __launch_bounds__(256) void encoder_kernel(const float* __restrict__ x,
                                                      const float* __restrict__ We,
                                                      const float* __restrict__ be){
    __shared__ __align__(16) float WeT[Dz*Hz];
    __shared__ float xs[32*Dz];
    int t = threadIdx.x;
    int m0 = blockIdx.x * 32;
    for (int i = t; i < Dz*Hz; i += 256){ int h = i >> 6, k = i & 63; WeT[k*Hz + h] = We[i]; }
    for (int i = t; i < 32*Dz; i += 256) xs[i] = x[(size_t)m0*Dz + i];
    __syncthreads();
    int r = t >> 3, hg = t & 7;
    float acc[16];
    #pragma unroll
    for (int j = 0; j < 16; j++) acc[j] = 0.f;
    #pragma unroll 4
    for (int k = 0; k < Dz; k++){
        float xv = xs[r*Dz + k];
        const float4* wp = (const float4*)&WeT[k*Hz + hg*16];
        float4 w0 = wp[0], w1 = wp[1], w2 = wp[2], w3 = wp[3];
        acc[0]=fmaf(xv,w0.x,acc[0]);   acc[1]=fmaf(xv,w0.y,acc[1]);
        acc[2]=fmaf(xv,w0.z,acc[2]);   acc[3]=fmaf(xv,w0.w,acc[3]);
        acc[4]=fmaf(xv,w1.x,acc[4]);   acc[5]=fmaf(xv,w1.y,acc[5]);
        acc[6]=fmaf(xv,w1.z,acc[6]);   acc[7]=fmaf(xv,w1.w,acc[7]);
        acc[8]=fmaf(xv,w2.x,acc[8]);   acc[9]=fmaf(xv,w2.y,acc[9]);
        acc[10]=fmaf(xv,w2.z,acc[10]); acc[11]=fmaf(xv,w2.w,acc[11]);
        acc[12]=fmaf(xv,w3.x,acc[12]); acc[13]=fmaf(xv,w3.y,acc[13]);
        acc[14]=fmaf(xv,w3.z,acc[14]); acc[15]=fmaf(xv,w3.w,acc[15]);
    }
    int m = m0 + r;
    #pragma unroll
    for (int j = 0; j < 16; j++){
        int h = hg*16 + j;
        g_pt[(size_t)m*Hz + h] = acc[j] + be[h];
    }
}

// ============================ 2) repeat flags ============================
__global__ void rep_kernel(const float* __restrict__ x){
    int s = blockIdx.x;
    int ok;
    if (s > 0){
        ok = 1;
        for (int i = threadIdx.x; i < Bz*Dz; i += 256){
            int b = i >> 6, d = i & 63;
            size_t idx = ((size_t)b*Sz + s)*Dz + d;
            if (x[idx] != x[idx - Dz]) { ok = 0; break; }
        }
    } else ok = 0;
    ok = __syncthreads_and(ok);
    if (threadIdx.x == 0) g_rep[s] = ok;
}

// ============================ 3) recurrence ============================
__global__ __launch_bounds__(128) void recur_kernel(const float* __restrict__ omega,
                                                    float* __restrict__ out_ph,
                                                    float* __restrict__ out_wb){
    __shared__ int reps[Sz];
    int b = blockIdx.x, h = threadIdx.x;
    for (int i = h; i < Sz; i += 128) reps[i] = g_rep[i];
    __syncthreads();
    float om = omega[h];
    float ph = 0.f, wb = 0.f;
    const float* ptp = g_pt + (size_t)b*Sz*Hz + h;
    float* php = out_ph + (size_t)b*Sz*Hz + h;
    float* wbp = out_wb + (size_t)b*Sz*Hz + h;
    #pragma unroll 8
    for (int s = 0; s < Sz; s++){
        float pt = ptp[(size_t)s*Hz];
        wb += 0.015625f;
        float drive = fmaf(0.25f, fsin(wb), om);       // off the ph critical path
        float phn = (ph + drive) - fsin(pt - ph);
        if (reps[s]) wb += 0.25f*fsin(pt - wb);
        ph = phn;
        php[(size_t)s*Hz] = ph;
        wbp[(size_t)s*Hz] = wb;
    }
}

// ============================ 4) weight permute (fp16) ============================
// g_Bp[n][k], k = h*8+jf. jf 0..5: trig weights; jf 6 (ph_hi) and 7 (ph_lo) both get w6.
__global__ void bperm_kernel(const float* __restrict__ Wr){
    int i = blockIdx.x*256 + threadIdx.x;
    if (i < Oz*Kz){
        int n = i >> 10, k = i & 1023;
        int h = k >> 3, jf = k & 7;
        if (jf > 6) jf = 6;
        g_Bp[i] = __float2half(Wr[n*(7*Hz) + jf*Hz + h]);
    }
}

// ============================ 5) fused readout GEMM (mma.sync HMMA) ============================
// logits[128m x 512n] = A[m x 1024k fp16 on-the-fly] x B[n x 1024k fp16] + br
// CTA 256 thr: tile 128m x 128n; warp 32m x 64n; 16 K-chunks of 64.
__global__ __launch_bounds__(256)
void readout_kernel(const float* __restrict__ ph_in, const float* __restrict__ wb_in,
                    const float* __restrict__ br, float* __restrict__ out){
    __shared__ __align__(128) __half As[128*64];   // 16KB, SW128 swizzled [m][k]
    __shared__ __align__(128) __half Bs[128*64];   // 16KB, SW128 swizzled [n][k]
    __shared__ float brs[512];

    int t = threadIdx.x, wid = t >> 5, lane = t & 31;
    int m0 = blockIdx.x * 128, n0 = blockIdx.y * 128;
    int wm = wid & 3, wn = wid >> 2;               // warp: 32 m-rows, 64 n-cols

    for (int i = t; i < Oz; i += 256) brs[i] = br[i];

    uint32_t As_b = smem_u32(As), Bs_b = smem_u32(Bs);

    // precomputed lane row/col pieces for ldmatrix addressing
    int a_row = wm*32 + (lane & 7) + ((lane >> 3) & 1)*8;   // + mt*16
    int a_kh  = (lane >> 4)*8;                              // + ks*16
    int b_row = wn*64 + (lane & 7) + (lane >> 4)*8;         // + ntp*16
    int b_kh  = ((lane >> 3) & 1)*8;                        // + ks*16

    float acc[2][8][4];
    #pragma unroll
    for (int mt = 0; mt < 2; mt++)
        #pragma unroll
        for (int nt = 0; nt < 8; nt++)
            #pragma unroll
            for (int v = 0; v < 4; v++) acc[mt][nt][v] = 0.f;

    for (int c = 0; c < 16; c++){
        // ---- generate A chunk: 128 m x (8 h x 8 jf) fp16 ----
        #pragma unroll
        for (int it = 0; it < 4; it++){
            int i = t + it*256;
            int m = i >> 3, hl = i & 7, h = c*8 + hl;
            float ph = ph_in[(size_t)(m0 + m)*Hz + h];
            float wb = wb_in[(size_t)(m0 + m)*Hz + h];
            float s2, c2; fsincos(0.5f*ph, &s2, &c2);
            float c1 = fmaf(2.f*c2, c2, -1.f);
            float s1 = 2.f*s2*c2;
            float s3, c3; fsincos(wb, &s3, &c3);
            __half hhi = __float2half(ph);
            __half hlo = __float2half(ph - __half2float(hhi));
            uint4 v;
            v.x = h2_to_u32(__floats2half2_rn(c1, s1));
            v.y = h2_to_u32(__floats2half2_rn(c2, s2));
            v.z = h2_to_u32(__floats2half2_rn(c3, s3));
            v.w = h2_to_u32(__halves2half2(hhi, hlo));
            *(uint4*)((char*)As + swz((uint32_t)(m*128 + hl*16))) = v;
        }
        // ---- load B chunk: 128 n x 64 k fp16 (L2-resident) ----
        const uint4* bsrc = (const uint4*)g_Bp;
        #pragma unroll
        for (int it = 0; it < 4; it++){
            int i = t + it*256;
            int n = i >> 3, k16 = i & 7;
            uint4 v = bsrc[(size_t)(n0 + n)*128 + c*8 + k16];
            *(uint4*)((char*)Bs + swz((uint32_t)(n*128 + k16*16))) = v;
        }
        __syncthreads();
        // ---- compute: 4 k-steps of 16 ----
        #pragma unroll
        for (int ks = 0; ks < 4; ks++){
            uint32_t af[2][4];
            #pragma unroll
            for (int mt = 0; mt < 2; mt++)
                ldsm_x4(af[mt], As_b + swz((uint32_t)((a_row + mt*16)*128 + (ks*16 + a_kh)*2)));
            uint32_t bf[4][4];
            #pragma unroll
            for (int ntp = 0; ntp < 4; ntp++)
                ldsm_x4(bf[ntp], Bs_b + swz((uint32_t)((b_row + ntp*16)*128 + (ks*16 + b_kh)*2)));
            #pragma unroll
            for (int mt = 0; mt < 2; mt++)
                #pragma unroll
                for (int nt = 0; nt < 8; nt++)
                    mma16816(acc[mt][nt], af[mt], &bf[nt >> 1][(nt & 1)*2]);
        }
        __syncthreads();
    }

    // ---- epilogue: frags + br -> gmem ----
    int lr = lane >> 2, lc = (lane & 3)*2;
    #pragma unroll
    for (int mt = 0; mt < 2; mt++){
        #pragma unroll
        for (int nt = 0; nt < 8; nt++){
            int m = m0 + wm*32 + mt*16 + lr;
            int n = n0 + wn*64 + nt*8 + lc;
            float b0 = brs[n], b1 = brs[n + 1];
            float2 v0 = make_float2(acc[mt][nt][0] + b0, acc[mt][nt][1] + b1);
            float2 v1 = make_float2(acc[mt][nt][2] + b0, acc[mt][nt][3] + b1);
            *(float2*)&out[(size_t)m*Oz + n]       = v0;
            *(float2*)&out[(size_t)(m + 8)*Oz + n] = v1;
        }
    }
}

// ============================ launch ============================
extern "C" void kernel_launch(void* const* d_in, const int* in_sizes, int n_in,
                              void* d_out, int out_size){
    const float* x     = (const float*)d_in[0];
    const float* We    = (const float*)d_in[1];
    const float* be    = (const float*)d_in[2];
    const float* omega = (const float*)d_in[3];
    const float* Wr    = (const float*)d_in[4];
    const float* br    = (const float*)d_in[5];
    float* out        = (float*)d_out;
    float* out_logits = out;                       // [B,S,O]
    float* out_ph     = out + (size_t)Mz*Oz;       // [B,S,H]
    float* out_wb     = out_ph + (size_t)Mz*Hz;    // [B,S,H]

    encoder_kernel<<<Mz/32, 256>>>(x, We, be);
    rep_kernel<<<Sz, 256>>>(x);
    bperm_kernel<<<(Oz*Kz + 255)/256, 256>>>(Wr);
    recur_kernel<<<Bz, 128>>>(omega, out_ph, out_wb);
    readout_kernel<<<dim3(Mz/128, Oz/128), 256>>>(out_ph, out_wb, br, out_logits);
}

// round 8
// speedup vs baseline: 4.4295x; 1.5085x over previous
#include <cuda_runtime.h>
#include <cuda_fp16.h>
#include <cstdint>

#define Bz 128
#define Sz 1024
#define Dz 64
#define Hz 128
#define Oz 512
#define Mz (Bz*Sz)   /* 131072 */
#define Kz 1024      /* 8 fp16 feature cols per h * 128 h */
#define PI_F 3.14159265358979f
#define TWO_PI_F 6.28318530717959f

// ---- static device scratch ----
__device__ float g_pt [(size_t)Mz*Hz];                 // encoder output, PRE-WRAPPED to (-pi,pi]
__device__ __align__(16) __half g_Bp[(size_t)Oz*Kz];   // permuted fp16 weights [n][k], k=h*8+jf
__device__ int   g_rep[Sz];

// ============================ helpers ============================
__device__ __forceinline__ uint32_t h2_to_u32(__half2 v){
    return *reinterpret_cast<uint32_t*>(&v);
}
__device__ __forceinline__ uint32_t smem_u32(const void* p){
    uint32_t a;
    asm("{ .reg .u64 t; cvta.to.shared.u64 t, %1; cvt.u32.u64 %0, t; }" : "=r"(a) : "l"(p));
    return a;
}
__device__ __forceinline__ uint32_t swz(uint32_t b){ return b ^ ((b >> 3) & 0x70); }

__device__ __forceinline__ void ldsm_x4(uint32_t* r, uint32_t addr){
    asm volatile("ldmatrix.sync.aligned.m8n8.x4.shared.b16 {%0,%1,%2,%3}, [%4];"
        : "=r"(r[0]), "=r"(r[1]), "=r"(r[2]), "=r"(r[3]) : "r"(addr));
}
__device__ __forceinline__ void mma16816(float* d, const uint32_t* a, const uint32_t* b){
    asm volatile("mma.sync.aligned.m16n8k16.row.col.f32.f16.f16.f32 "
        "{%0,%1,%2,%3}, {%4,%5,%6,%7}, {%8,%9}, {%0,%1,%2,%3};"
        : "+f"(d[0]), "+f"(d[1]), "+f"(d[2]), "+f"(d[3])
        : "r"(a[0]), "r"(a[1]), "r"(a[2]), "r"(a[3]), "r"(b[0]), "r"(b[1]));
}
__device__ __forceinline__ void cp_async16(uint32_t dst, const void* src){
    asm volatile("cp.async.cg.shared.global [%0], [%1], 16;" :: "r"(dst), "l"(src));
}
#define CP_COMMIT() asm volatile("cp.async.commit_group;" ::: "memory")
#define CP_WAIT0()  asm volatile("cp.async.wait_group 0;" ::: "memory")

// ---- fast sin/sincos with magic-number range reduction ----
__device__ __forceinline__ float wrap_pi(float x){
    float k = fmaf(x, 0.15915494309189535f, 12582912.0f);
    k -= 12582912.0f;
    float r = fmaf(k, -6.28125f, x);
    r = fmaf(k, -1.9353071795864769e-3f, r);
    return r;
}
__device__ __forceinline__ float fsin(float x){ return __sinf(wrap_pi(x)); }
__device__ __forceinline__ void fsincos(float x, float* s, float* c){ __sincosf(wrap_pi(x), s, c); }

// ============================ 1) encoder (stores wrapped pt) ============================
__global__ __launch_bounds__(256) void encoder_kernel(const float* __restrict__ x,
                                                      const float* __restrict__ We,
                                                      const float* __restrict__ be){
    __shared__ __align__(16) float WeT[Dz*Hz];
    __shared__ float xs[32*Dz];
    int t = threadIdx.x;
    int m0 = blockIdx.x * 32;
    for (int i = t; i < Dz*Hz; i += 256){ int h = i >> 6, k = i & 63; WeT[k*Hz + h] = We[i]; }
    for (int i = t; i < 32*Dz; i += 256) xs[i] = x[(size_t)m0*Dz + i];
    __syncthreads();
    int r = t >> 3, hg = t & 7;
    float acc[16];
    #pragma unroll
    for (int j = 0; j < 16; j++) acc[j] = 0.f;
    #pragma unroll 4
    for (int k = 0; k < Dz; k++){
        float xv = xs[r*Dz + k];
        const float4* wp = (const float4*)&WeT[k*Hz + hg*16];
        float4 w0 = wp[0], w1 = wp[1], w2 = wp[2], w3 = wp[3];
        acc[0]=fmaf(xv,w0.x,acc[0]);   acc[1]=fmaf(xv,w0.y,acc[1]);
        acc[2]=fmaf(xv,w0.z,acc[2]);   acc[3]=fmaf(xv,w0.w,acc[3]);
        acc[4]=fmaf(xv,w1.x,acc[4]);   acc[5]=fmaf(xv,w1.y,acc[5]);
        acc[6]=fmaf(xv,w1.z,acc[6]);   acc[7]=fmaf(xv,w1.w,acc[7]);
        acc[8]=fmaf(xv,w2.x,acc[8]);   acc[9]=fmaf(xv,w2.y,acc[9]);
        acc[10]=fmaf(xv,w2.z,acc[10]); acc[11]=fmaf(xv,w2.w,acc[11]);
        acc[12]=fmaf(xv,w3.x,acc[12]); acc[13]=fmaf(xv,w3.y,acc[13]);
        acc[14]=fmaf(xv,w3.z,acc[14]); acc[15]=fmaf(xv,w3.w,acc[15]);
    }
    int m = m0 + r;
    #pragma unroll
    for (int j = 0; j < 16; j++){
        int h = hg*16 + j;
        g_pt[(size_t)m*Hz + h] = wrap_pi(acc[j] + be[h]);
    }
}

// ============================ 2) repeat flags ============================
__global__ void rep_kernel(const float* __restrict__ x){
    int s = blockIdx.x;
    int ok;
    if (s > 0){
        ok = 1;
        for (int i = threadIdx.x; i < Bz*Dz; i += 256){
            int b = i >> 6, d = i & 63;
            size_t idx = ((size_t)b*Sz + s)*Dz + d;
            if (x[idx] != x[idx - Dz]) { ok = 0; break; }
        }
    } else ok = 0;
    ok = __syncthreads_and(ok);
    if (threadIdx.x == 0) g_rep[s] = ok;
}

// ============================ 3) recurrence ============================
// phw: folded copy of ph in (-pi-eps, pi+eps]; sin(pt - ph) == sin(pt_w - phw), |arg| < 2pi.
// Wobble drive 0.25*sin(wb) is block-uniform until first repeat -> smem table fast path.
__global__ __launch_bounds__(128) void recur_kernel(const float* __restrict__ omega,
                                                    float* __restrict__ out_ph,
                                                    float* __restrict__ out_wb){
    __shared__ float tbl[Sz];      // 0.25*sin((s+1)*WOBBLE_STEP)
    __shared__ int   reps[Sz];
    __shared__ int   any8[Sz/8];   // OR of reps over groups of 8
    int b = blockIdx.x, h = threadIdx.x;
    for (int i = h; i < Sz; i += 128){
        reps[i] = g_rep[i];
        tbl[i]  = 0.25f*fsin(0.015625f*(float)(i+1));
    }
    __syncthreads();
    for (int i = h; i < Sz/8; i += 128){
        int a = 0;
        #pragma unroll
        for (int j = 0; j < 8; j++) a |= reps[i*8 + j];
        any8[i] = a;
    }
    __syncthreads();

    float om = omega[h];
    float ph = 0.f, phw = 0.f, wb = 0.f;
    bool div = false;
    const float* ptp = g_pt + (size_t)b*Sz*Hz + h;
    float* php = out_ph + (size_t)b*Sz*Hz + h;
    float* wbp = out_wb + (size_t)b*Sz*Hz + h;

    for (int s0 = 0; s0 < Sz; s0 += 8){
        float pts[8];
        #pragma unroll
        for (int j = 0; j < 8; j++) pts[j] = ptp[(size_t)(s0 + j)*Hz];
        if (!div && !any8[s0 >> 3]){
            // fast path: no repeats in this group, wobble drive from table
            #pragma unroll
            for (int j = 0; j < 8; j++){
                int s = s0 + j;
                wb += 0.015625f;
                float c = om + tbl[s];
                float d = pts[j] - phw;
                float t = c - __sinf(d);
                ph  += t;
                phw += t;
                phw += (phw > PI_F) ? -TWO_PI_F : ((phw < -PI_F) ? TWO_PI_F : 0.f);
                php[(size_t)s*Hz] = ph;
                wbp[(size_t)s*Hz] = wb;
            }
        } else {
            // careful path: full semantics
            #pragma unroll
            for (int j = 0; j < 8; j++){
                int s = s0 + j;
                wb += 0.015625f;
                float c = om + 0.25f*fsin(wb);
                float d = pts[j] - phw;
                float t = c - __sinf(d);
                float phn  = ph + t;
                float phwn = phw + t;
                if (reps[s]) { wb += 0.25f*fsin(pts[j] - wb); div = true; }
                ph = phn; phw = phwn;
                phw += (phw > PI_F) ? -TWO_PI_F : ((phw < -PI_F) ? TWO_PI_F : 0.f);
                php[(size_t)s*Hz] = ph;
                wbp[(size_t)s*Hz] = wb;
            }
        }
    }
}

// ============================ 4) weight permute (fp16) ============================
__global__ void bperm_kernel(const float* __restrict__ Wr){
    int i = blockIdx.x*256 + threadIdx.x;
    if (i < Oz*Kz){
        int n = i >> 10, k = i & 1023;
        int h = k >> 3, jf = k & 7;
        if (jf > 6) jf = 6;
        g_Bp[i] = __float2half(Wr[n*(7*Hz) + jf*Hz + h]);
    }
}

// ============================ 5) fused readout GEMM (HMMA, double-buffered) ============================
// smem layout (dynamic): A0 @0 (16KB), A1 @16384, B0 @32768, B1 @49152, brs @65536 (2KB)
#define RD_SMEM (65536 + 2048)

__global__ __launch_bounds__(256)
void readout_kernel(const float* __restrict__ ph_in, const float* __restrict__ wb_in,
                    const float* __restrict__ br, float* __restrict__ out){
    extern __shared__ __align__(128) char smem[];
    char* Asm = smem;             // 2 x 16KB
    char* Bsm = smem + 32768;     // 2 x 16KB
    float* brs = (float*)(smem + 65536);

    int t = threadIdx.x, wid = t >> 5, lane = t & 31;
    int n0 = blockIdx.x * 128, m0 = blockIdx.y * 128;   // n fastest -> same-m blocks concurrent
    int wm = wid & 3, wn = wid >> 2;

    for (int i = t; i < Oz; i += 256) brs[i] = br[i];

    uint32_t As_b = smem_u32(Asm), Bs_b = smem_u32(Bsm);

    // gen-thread mapping: i = t + it*256 -> m = i>>3, hl = i&7
    int gm = t >> 3, ghl = t & 7;

    // ldmatrix lane addressing (same as R7, verified)
    int a_row = wm*32 + (lane & 7) + ((lane >> 3) & 1)*8;
    int a_kh  = (lane >> 4)*8;
    int b_row = wn*64 + (lane & 7) + (lane >> 4)*8;
    int b_kh  = ((lane >> 3) & 1)*8;

    float acc[2][8][4];
    #pragma unroll
    for (int mt = 0; mt < 2; mt++)
        #pragma unroll
        for (int nt = 0; nt < 8; nt++)
            #pragma unroll
            for (int v = 0; v < 4; v++) acc[mt][nt][v] = 0.f;

    const uint4* bsrc = (const uint4*)g_Bp;
    // B cp.async mapping: i = t + it*256 -> n = i>>3, k16 = i&7
    int bn = t >> 3, bk16 = t & 7;

    // ---- prologue: chunk 0 ----
    {
        // B0 via cp.async
        #pragma unroll
        for (int it = 0; it < 4; it++){
            int n = bn + it*32;
            cp_async16(Bs_b + swz((uint32_t)(n*128 + bk16*16)),
                       &bsrc[(size_t)(n0 + n)*128 + 0*8 + bk16]);
        }
        CP_COMMIT();
        // A0 synchronously
        #pragma unroll
        for (int it = 0; it < 4; it++){
            int m = gm + it*32, h = 0*8 + ghl;
            float ph = ph_in[(size_t)(m0 + m)*Hz + h];
            float wb = wb_in[(size_t)(m0 + m)*Hz + h];
            float s2, c2; fsincos(0.5f*ph, &s2, &c2);
            float c1 = fmaf(2.f*c2, c2, -1.f);
            float s1 = 2.f*s2*c2;
            float s3, c3; fsincos(wb, &s3, &c3);
            __half hhi = __float2half(ph);
            __half hlo = __float2half(ph - __half2float(hhi));
            uint4 v;
            v.x = h2_to_u32(__floats2half2_rn(c1, s1));
            v.y = h2_to_u32(__floats2half2_rn(c2, s2));
            v.z = h2_to_u32(__floats2half2_rn(c3, s3));
            v.w = h2_to_u32(__halves2half2(hhi, hlo));
            *(uint4*)(Asm + swz((uint32_t)(m*128 + ghl*16))) = v;
        }
        CP_WAIT0();
        __syncthreads();
    }

    for (int c = 0; c < 16; c++){
        int cur = c & 1, nxt = cur ^ 1;
        float pr[4], wr[4];
        if (c < 15){
            // issue next B loads (async) + next ph/wb loads (regs) — latency hidden by MMA
            #pragma unroll
            for (int it = 0; it < 4; it++){
                int n = bn + it*32;
                cp_async16(Bs_b + (uint32_t)(nxt*16384) + swz((uint32_t)(n*128 + bk16*16)),
                           &bsrc[(size_t)(n0 + n)*128 + (c+1)*8 + bk16]);
            }
            CP_COMMIT();
            int h = (c+1)*8 + ghl;
            #pragma unroll
            for (int it = 0; it < 4; it++){
                int m = gm + it*32;
                pr[it] = ph_in[(size_t)(m0 + m)*Hz + h];
                wr[it] = wb_in[(size_t)(m0 + m)*Hz + h];
            }
        }
        // ---- MMA on cur ----
        uint32_t Ab = As_b + (uint32_t)(cur*16384);
        uint32_t Bb = Bs_b + (uint32_t)(cur*16384);
        #pragma unroll
        for (int ks = 0; ks < 4; ks++){
            uint32_t af[2][4];
            #pragma unroll
            for (int mt = 0; mt < 2; mt++)
                ldsm_x4(af[mt], Ab + swz((uint32_t)((a_row + mt*16)*128 + (ks*16 + a_kh)*2)));
            uint32_t bf[4][4];
            #pragma unroll
            for (int ntp = 0; ntp < 4; ntp++)
                ldsm_x4(bf[ntp], Bb + swz((uint32_t)((b_row + ntp*16)*128 + (ks*16 + b_kh)*2)));
            #pragma unroll
            for (int mt = 0; mt < 2; mt++)
                #pragma unroll
                for (int nt = 0; nt < 8; nt++)
                    mma16816(acc[mt][nt], af[mt], &bf[nt >> 1][(nt & 1)*2]);
        }
        if (c < 15){
            // trig + store A(c+1) into nxt
            #pragma unroll
            for (int it = 0; it < 4; it++){
                int m = gm + it*32;
                float ph = pr[it], wb = wr[it];
                float s2, c2; fsincos(0.5f*ph, &s2, &c2);
                float c1 = fmaf(2.f*c2, c2, -1.f);
                float s1 = 2.f*s2*c2;
                float s3, c3; fsincos(wb, &s3, &c3);
                __half hhi = __float2half(ph);
                __half hlo = __float2half(ph - __half2float(hhi));
                uint4 v;
                v.x = h2_to_u32(__floats2half2_rn(c1, s1));
                v.y = h2_to_u32(__floats2half2_rn(c2, s2));
                v.z = h2_to_u32(__floats2half2_rn(c3, s3));
                v.w = h2_to_u32(__halves2half2(hhi, hlo));
                *(uint4*)(Asm + nxt*16384 + swz((uint32_t)(m*128 + ghl*16))) = v;
            }
            CP_WAIT0();
        }
        __syncthreads();
    }

    // ---- epilogue ----
    int lr = lane >> 2, lc = (lane & 3)*2;
    #pragma unroll
    for (int mt = 0; mt < 2; mt++){
        #pragma unroll
        for (int nt = 0; nt < 8; nt++){
            int m = m0 + wm*32 + mt*16 + lr;
            int n = n0 + wn*64 + nt*8 + lc;
            float b0 = brs[n], b1 = brs[n + 1];
            float2 v0 = make_float2(acc[mt][nt][0] + b0, acc[mt][nt][1] + b1);
            float2 v1 = make_float2(acc[mt][nt][2] + b0, acc[mt][nt][3] + b1);
            *(float2*)&out[(size_t)m*Oz + n]       = v0;
            *(float2*)&out[(size_t)(m + 8)*Oz + n] = v1;
        }
    }
}

// ============================ launch ============================
extern "C" void kernel_launch(void* const* d_in, const int* in_sizes, int n_in,
                              void* d_out, int out_size){
    const float* x     = (const float*)d_in[0];
    const float* We    = (const float*)d_in[1];
    const float* be    = (const float*)d_in[2];
    const float* omega = (const float*)d_in[3];
    const float* Wr    = (const float*)d_in[4];
    const float* br    = (const float*)d_in[5];
    float* out        = (float*)d_out;
    float* out_logits = out;                       // [B,S,O]
    float* out_ph     = out + (size_t)Mz*Oz;       // [B,S,H]
    float* out_wb     = out_ph + (size_t)Mz*Hz;    // [B,S,H]

    cudaFuncSetAttribute(readout_kernel, cudaFuncAttributeMaxDynamicSharedMemorySize, RD_SMEM);

    encoder_kernel<<<Mz/32, 256>>>(x, We, be);
    rep_kernel<<<Sz, 256>>>(x);
    bperm_kernel<<<(Oz*Kz + 255)/256, 256>>>(Wr);
    recur_kernel<<<Bz, 128>>>(omega, out_ph, out_wb);
    readout_kernel<<<dim3(Oz/128, Mz/128), 256, RD_SMEM>>>(out_ph, out_wb, br, out_logits);
}